// round 15
// baseline (speedup 1.0000x reference)
#include <cuda_runtime.h>
#include <cuda_bf16.h>
#include <cstdint>

// vanillaMLP fused. Round 15: round-14 occupancy fix (acc spill to smem,
// launch_bounds(128,5)) with the 6th GEMM1 MMA (am*bm, ~2^-16 relative — NOT
// negligible) restored. Numerics identical to round-13 (passed, 3.5e-4).
// Outputs: [sigma N | fea N*16 | normals N*3 | grad N*3]

#define T_SIZE  524288
#define T_MASK  (T_SIZE - 1)
#define PRIME_Y 2654435761u
#define PRIME_Z 805459861u
#define DENSITY_BIAS (-1.0f)
#define CLAMP_MAX 10.0f
#define EXP10F 22026.465794806718f

#define D0 18
#define D1 24
#define D2 32
#define D3 44
#define OFF0 0
#define OFF1 5832
#define OFF2 19656
#define OFF3 52424
#define NDENSE 137608
#define NREC (NDENSE * 4)

// weight fragments:
//   B1[3][8][32] | B2[2][8][2][32] | B3[2][8][32] | W2R0[2][8][4]
#define WF_B1(s, t)      ((s) * 256 + (t) * 32)
#define WF_B2(s, t, nt)  (768 + (s) * 512 + (t) * 64 + (nt) * 32)
#define WF_B3(s, t)      (1792 + (s) * 256 + (t) * 32)
#define WF_W2R0(s, t)    (2304 + (s) * 32 + (t) * 4)
#define WF_TOTAL 2368

__device__ __align__(128) float4   g_rec[NREC + 8];
__device__ uint32_t g_frag[WF_TOTAL];

typedef unsigned long long u64;
typedef uint32_t u32;

__device__ __forceinline__ u64 pk(float a, float b) {
    u64 r; asm("mov.b64 %0, {%1,%2};" : "=l"(r) : "f"(a), "f"(b)); return r;
}
__device__ __forceinline__ u64 pk2(float a) { return pk(a, a); }
__device__ __forceinline__ float2 upk(u64 v) {
    float2 r; asm("mov.b64 {%0,%1}, %2;" : "=f"(r.x), "=f"(r.y) : "l"(v)); return r;
}
__device__ __forceinline__ u64 fma2(u64 a, u64 b, u64 c) {
    u64 d; asm("fma.rn.f32x2 %0, %1, %2, %3;" : "=l"(d) : "l"(a), "l"(b), "l"(c)); return d;
}
__device__ __forceinline__ u64 mul2(u64 a, u64 b) {
    u64 d; asm("mul.rn.f32x2 %0, %1, %2;" : "=l"(d) : "l"(a), "l"(b)); return d;
}
__device__ __forceinline__ u64 add2(u64 a, u64 b) {
    u64 d; asm("add.rn.f32x2 %0, %1, %2;" : "=l"(d) : "l"(a), "l"(b)); return d;
}
__device__ __forceinline__ u64 neg2(u64 a) { return a ^ 0x8000000080000000ULL; }
__device__ __forceinline__ uint2 u64_to_u2(u64 a) { return make_uint2((u32)a, (u32)(a >> 32)); }
__device__ __forceinline__ u64 u2_to_u64(uint2 v) { return ((u64)v.y << 32) | v.x; }

__device__ __forceinline__ void mma8(float& c0, float& c1, float& c2, float& c3,
                                     u32 a0, u32 a1, u32 b0) {
    asm volatile("mma.sync.aligned.m16n8k8.row.col.f32.bf16.bf16.f32 "
                 "{%0,%1,%2,%3}, {%4,%5}, {%6}, {%0,%1,%2,%3};"
                 : "+f"(c0), "+f"(c1), "+f"(c2), "+f"(c3)
                 : "r"(a0), "r"(a1), "r"(b0));
}

__device__ __forceinline__ u32 pkbf_rn(float a, float b) {
    __nv_bfloat16 ba = __float2bfloat16(a), bb = __float2bfloat16(b);
    return ((u32)__bfloat16_as_ushort(bb) << 16) | __bfloat16_as_ushort(ba);
}

// ---------------- setup: corner-records + weight fragments ----------------
__global__ void __launch_bounds__(256)
setup_kernel(const float* __restrict__ table,
             const float* __restrict__ W1,
             const float* __restrict__ W2)
{
    int idx = blockIdx.x * 256 + threadIdx.x;
    if (idx < NREC) {
        int cell = idx >> 2, q = idx & 3;
        int l, local, D;
        if (cell < OFF1)      { l = 0; local = cell;        D = D0; }
        else if (cell < OFF2) { l = 1; local = cell - OFF1; D = D1; }
        else if (cell < OFF3) { l = 2; local = cell - OFF2; D = D2; }
        else                  { l = 3; local = cell - OFF3; D = D3; }
        int z = local % D;
        int t = local / D;
        int y = t % D;
        int x = t / D;
        int ox = q >> 1, oy = q & 1;
        unsigned hb = (unsigned)(x + ox) ^ ((unsigned)(y + oy) * PRIME_Y);
        unsigned h0 = hb ^ ((unsigned)z * PRIME_Z);
        unsigned h1 = hb ^ ((unsigned)(z + 1) * PRIME_Z);
        const float2* __restrict__ tbl = (const float2*)table + (size_t)l * T_SIZE;
        float2 a = __ldg(tbl + (h0 & T_MASK));
        float2 b = __ldg(tbl + (h1 & T_MASK));
        g_rec[idx] = make_float4(a.x, a.y, b.x, b.y);
    }
    if (blockIdx.x == 1) {
        for (int i = threadIdx.x; i < WF_TOTAL; i += 256) {
            float va, vb;
            int s;
            if (i < 768) {
                s = i >> 8; int r = i & 255; int t = r >> 5, lane = r & 31;
                int g = lane >> 2, c = lane & 3;
                va = W1[(t * 8 + g) * 32 + 2 * c];
                vb = W1[(t * 8 + g) * 32 + 2 * c + 1];
            } else if (i < 1792) {
                int r = i - 768; s = r >> 9; r &= 511;
                int kt = r >> 6; int nt = (r >> 5) & 1; int lane = r & 31;
                int g = lane >> 2, c = lane & 3;
                va = W2[(nt * 8 + g) * 64 + kt * 8 + 2 * c];
                vb = W2[(nt * 8 + g) * 64 + kt * 8 + 2 * c + 1];
            } else if (i < 2304) {
                int r = i - 1792; s = r >> 8; r &= 255;
                int kt = r >> 5; int lane = r & 31;
                int g = lane >> 2, c = lane & 3;
                va = W1[(kt * 8 + 2 * c) * 32 + g];
                vb = W1[(kt * 8 + 2 * c + 1) * 32 + g];
            } else {
                int r = i - 2304; s = r >> 5; r &= 31;
                int t = r >> 2; int c = r & 3;
                va = W2[t * 8 + 2 * c];
                vb = W2[t * 8 + 2 * c + 1];
            }
            for (int it = 0; it < s; it++) {
                va -= __bfloat162float(__float2bfloat16(va));
                vb -= __bfloat162float(__float2bfloat16(vb));
            }
            g_frag[i] = pkbf_rn(va, vb);
        }
    }
}

// ---------------- smem layout ----------------
#define SM_STAGE_A 0
#define SM_STAGE_B 10240
#define SM_WFRAG   20480
#define SM_ACC     (20480 + WF_TOTAL * 4)
#define SM_TOTAL   (SM_ACC + 14336)

__global__ void __launch_bounds__(128, 5)
nerf_fused_kernel(const float* __restrict__ pts,
                  float* __restrict__ out,
                  int n)
{
    __shared__ __align__(16) char smem[SM_TOTAL];
    float4* sbufA = (float4*)(smem + SM_STAGE_A);
    float4* sbufB = (float4*)(smem + SM_STAGE_B);
    u32*    wf    = (u32*)(smem + SM_WFRAG);

    const int tid  = threadIdx.x;
    const int w    = tid >> 5;
    const int lane = tid & 31;

    for (int i = tid; i < WF_TOTAL; i += 128) wf[i] = g_frag[i];

    // coalesced point load through sbufA
    float* sf = (float*)sbufA;
    {
        size_t base = (size_t)blockIdx.x * 384;
        size_t lim3 = (size_t)n * 3;
        for (int i = tid; i < 384; i += 128) {
            size_t gi = base + i;
            sf[i] = (gi < lim3) ? pts[gi] : 0.0f;
        }
    }
    __syncthreads();

    const int pid = blockIdx.x * 128 + tid;
    const bool active = (pid < n);

    float x = (sf[tid * 3 + 0] + 1.0f) * 0.5f;
    float y = (sf[tid * 3 + 1] + 1.0f) * 0.5f;
    float z = (sf[tid * 3 + 2] + 1.0f) * 0.5f;
    __syncthreads();

    const float RES[4]  = {16.0f, 22.0f, 30.0f, 42.0f};
    const int   DIMS[4] = {D0, D1, D2, D3};
    const int   OFFS[4] = {OFF0, OFF1, OFF2, OFF3};

    const int qbase = lane & ~3;
    const int lq    = lane & 3;
    u32* accS = (u32*)(smem + SM_ACC) + tid * 28;

    u64 feat2[4];

    #pragma unroll
    for (int l = 0; l < 4; l++) {
        const float res = RES[l];
        const int   D   = DIMS[l];
        float fx = x * res, fy = y * res, fz = z * res;
        float x0 = floorf(fx), y0 = floorf(fy), z0 = floorf(fz);
        float frx = fx - x0, fry = fy - y0, frz = fz - z0;
        float mfx = 1.0f - frx, mfy = 1.0f - fry, mfz = 1.0f - frz;
        int rec = OFFS[l] + (((int)x0 * D + (int)y0) * D + (int)z0);

        float4* sb = (l & 1) ? sbufB : sbufA;
        #pragma unroll
        for (int i = 0; i < 4; i++) {
            int r = __shfl_sync(0xffffffffu, rec, qbase + i);
            float4 v = __ldg(g_rec + (size_t)r * 4 + lq);
            sb[((tid & ~31) + qbase + i) * 5 + lq] = v;
        }
        __syncwarp();
        float4 v00 = sb[tid * 5 + 0];
        float4 v01 = sb[tid * 5 + 1];
        float4 v10 = sb[tid * 5 + 2];
        float4 v11 = sb[tid * 5 + 3];

        u64 fz0 = pk2(mfz), fz1 = pk2(frz);
        u64 f01 = 0, ax = 0, ay = 0, az = 0;
        {   // (0,0)
            u64 t0 = pk(v00.x, v00.y), t1 = pk(v00.z, v00.w);
            u64 s = fma2(t0, fz0, mul2(t1, fz1));
            u64 d = add2(t1, neg2(t0));
            float wxy = mfx * mfy;
            f01 = fma2(pk2(wxy), s, f01);
            ax  = fma2(pk2(-mfy), s, ax);
            ay  = fma2(pk2(-mfx), s, ay);
            az  = fma2(pk2(wxy), d, az);
        }
        {   // (0,1)
            u64 t0 = pk(v01.x, v01.y), t1 = pk(v01.z, v01.w);
            u64 s = fma2(t0, fz0, mul2(t1, fz1));
            u64 d = add2(t1, neg2(t0));
            float wxy = mfx * fry;
            f01 = fma2(pk2(wxy), s, f01);
            ax  = fma2(pk2(-fry), s, ax);
            ay  = fma2(pk2( mfx), s, ay);
            az  = fma2(pk2(wxy), d, az);
        }
        {   // (1,0)
            u64 t0 = pk(v10.x, v10.y), t1 = pk(v10.z, v10.w);
            u64 s = fma2(t0, fz0, mul2(t1, fz1));
            u64 d = add2(t1, neg2(t0));
            float wxy = frx * mfy;
            f01 = fma2(pk2(wxy), s, f01);
            ax  = fma2(pk2( mfy), s, ax);
            ay  = fma2(pk2(-frx), s, ay);
            az  = fma2(pk2(wxy), d, az);
        }
        {   // (1,1)
            u64 t0 = pk(v11.x, v11.y), t1 = pk(v11.z, v11.w);
            u64 s = fma2(t0, fz0, mul2(t1, fz1));
            u64 d = add2(t1, neg2(t0));
            float wxy = frx * fry;
            f01 = fma2(pk2(wxy), s, f01);
            ax  = fma2(pk2( fry), s, ax);
            ay  = fma2(pk2( frx), s, ay);
            az  = fma2(pk2(wxy), d, az);
        }
        feat2[l] = f01;
        // spill encode partials (dead across MMA loop) to smem
        *(uint2*)(accS + l * 6 + 0) = u64_to_u2(ax);
        *(uint2*)(accS + l * 6 + 2) = u64_to_u2(ay);
        *(uint2*)(accS + l * 6 + 4) = u64_to_u2(az);
        __syncwarp();
    }

    __syncthreads();

    // ---- feat 3-way bf16 split -> fragment staging [warp][hi/mid/lo][32][4] ----
    u32* featHi  = (u32*)(smem + SM_STAGE_A + w * 1536);
    u32* featMid = featHi + 128;
    u32* featLo  = featHi + 256;
    {
        u32 fh[4], fm[4], fl[4];
        #pragma unroll
        for (int l = 0; l < 4; l++) {
            float2 f = upk(feat2[l]);
            __nv_bfloat16 h0 = __float2bfloat16(f.x), h1 = __float2bfloat16(f.y);
            fh[l] = ((u32)__bfloat16_as_ushort(h1) << 16) | __bfloat16_as_ushort(h0);
            float rx = f.x - __bfloat162float(h0);
            float ry = f.y - __bfloat162float(h1);
            __nv_bfloat16 m0 = __float2bfloat16(rx), m1 = __float2bfloat16(ry);
            fm[l] = ((u32)__bfloat16_as_ushort(m1) << 16) | __bfloat16_as_ushort(m0);
            float sx = rx - __bfloat162float(m0);
            float sy = ry - __bfloat162float(m1);
            fl[l] = pkbf_rn(sx, sy);
        }
        *(uint4*)(featHi  + lane * 4) = make_uint4(fh[0], fh[1], fh[2], fh[3]);
        *(uint4*)(featMid + lane * 4) = make_uint4(fm[0], fm[1], fm[2], fm[3]);
        *(uint4*)(featLo  + lane * 4) = make_uint4(fl[0], fl[1], fl[2], fl[3]);
    }
    __syncwarp();

    u32 ah[2][2], am[2][2], al[2][2];
    #pragma unroll
    for (int m = 0; m < 2; m++) {
        ah[m][0] = featHi[m * 64 + lane];   ah[m][1] = featHi[m * 64 + 32 + lane];
        am[m][0] = featMid[m * 64 + lane];  am[m][1] = featMid[m * 64 + 32 + lane];
        al[m][0] = featLo[m * 64 + lane];   al[m][1] = featLo[m * 64 + 32 + lane];
    }

    float fc[2][2][4];
    float dc[2][4];
    #pragma unroll
    for (int m = 0; m < 2; m++) {
        #pragma unroll
        for (int nt = 0; nt < 2; nt++)
            fc[m][nt][0] = fc[m][nt][1] = fc[m][nt][2] = fc[m][nt][3] = 0.0f;
        dc[m][0] = dc[m][1] = dc[m][2] = dc[m][3] = 0.0f;
    }

    #pragma unroll 2
    for (int t = 0; t < 8; t++) {
        u32 b1h = wf[WF_B1(0, t) + lane];
        u32 b1m = wf[WF_B1(1, t) + lane];
        u32 b1l = wf[WF_B1(2, t) + lane];
        u32 b2h0 = wf[WF_B2(0, t, 0) + lane], b2h1 = wf[WF_B2(0, t, 1) + lane];
        u32 b2l0 = wf[WF_B2(1, t, 0) + lane], b2l1 = wf[WF_B2(1, t, 1) + lane];
        u32 b3h = wf[WF_B3(0, t) + lane];
        u32 b3l = wf[WF_B3(1, t) + lane];
        u32 w2h = wf[WF_W2R0(0, t) + lq];
        u32 w2l = wf[WF_W2R0(1, t) + lq];

        #pragma unroll
        for (int m = 0; m < 2; m++) {
            // GEMM1: 6-MMA 3-way-split emulation (error ~2^-24 of |h|)
            float c0 = 0, c1 = 0, c2 = 0, c3 = 0;
            mma8(c0, c1, c2, c3, ah[m][0], ah[m][1], b1h);
            mma8(c0, c1, c2, c3, ah[m][0], ah[m][1], b1m);
            mma8(c0, c1, c2, c3, am[m][0], am[m][1], b1h);
            mma8(c0, c1, c2, c3, ah[m][0], ah[m][1], b1l);
            mma8(c0, c1, c2, c3, al[m][0], al[m][1], b1h);
            mma8(c0, c1, c2, c3, am[m][0], am[m][1], b1m);

            float h0 = fmaxf(c0, 0.0f), h1 = fmaxf(c1, 0.0f);
            float h2 = fmaxf(c2, 0.0f), h3 = fmaxf(c3, 0.0f);
            u32 u0 = __float_as_uint(h0), u1 = __float_as_uint(h1);
            u32 u2 = __float_as_uint(h2), u3 = __float_as_uint(h3);
            u32 a2h0 = __byte_perm(u0, u1, 0x7632);
            u32 a2h1 = __byte_perm(u2, u3, 0x7632);
            float r0 = h0 - __uint_as_float(u0 & 0xFFFF0000u);
            float r1 = h1 - __uint_as_float(u1 & 0xFFFF0000u);
            float r2 = h2 - __uint_as_float(u2 & 0xFFFF0000u);
            float r3 = h3 - __uint_as_float(u3 & 0xFFFF0000u);
            u32 a2l0 = __byte_perm(__float_as_uint(r0), __float_as_uint(r1), 0x7632);
            u32 a2l1 = __byte_perm(__float_as_uint(r2), __float_as_uint(r3), 0x7632);

            u32 mb0 = (c0 > 0.0f ? 0x0000FFFFu : 0u) | (c1 > 0.0f ? 0xFFFF0000u : 0u);
            u32 mb1 = (c2 > 0.0f ? 0x0000FFFFu : 0u) | (c3 > 0.0f ? 0xFFFF0000u : 0u);
            u32 mh0 = w2h & mb0, mh1 = w2h & mb1;
            u32 ml0 = w2l & mb0, ml1 = w2l & mb1;

            mma8(fc[m][0][0], fc[m][0][1], fc[m][0][2], fc[m][0][3], a2h0, a2h1, b2h0);
            mma8(fc[m][0][0], fc[m][0][1], fc[m][0][2], fc[m][0][3], a2h0, a2h1, b2l0);
            mma8(fc[m][0][0], fc[m][0][1], fc[m][0][2], fc[m][0][3], a2l0, a2l1, b2h0);
            mma8(fc[m][1][0], fc[m][1][1], fc[m][1][2], fc[m][1][3], a2h0, a2h1, b2h1);
            mma8(fc[m][1][0], fc[m][1][1], fc[m][1][2], fc[m][1][3], a2h0, a2h1, b2l1);
            mma8(fc[m][1][0], fc[m][1][1], fc[m][1][2], fc[m][1][3], a2l0, a2l1, b2h1);

            mma8(dc[m][0], dc[m][1], dc[m][2], dc[m][3], mh0, mh1, b3h);
            mma8(dc[m][0], dc[m][1], dc[m][2], dc[m][3], mh0, mh1, b3l);
            mma8(dc[m][0], dc[m][1], dc[m][2], dc[m][3], ml0, ml1, b3h);
        }
    }

    const int g = lane >> 2, cq = lane & 3;

    // ---- dacc frags -> per-warp smem [32][8], then own row back ----
    float* daccS = (float*)(smem + SM_STAGE_A + 6144 + w * 1024);
    #pragma unroll
    for (int m = 0; m < 2; m++) {
        *(float2*)(daccS + (m * 16 + g) * 8 + 2 * cq)     = make_float2(dc[m][0], dc[m][1]);
        *(float2*)(daccS + (m * 16 + g + 8) * 8 + 2 * cq) = make_float2(dc[m][2], dc[m][3]);
    }
    __syncwarp();
    u64 dacc2[4];
    #pragma unroll
    for (int l = 0; l < 4; l++)
        dacc2[l] = *(u64*)(daccS + lane * 8 + 2 * l);

    // ---- fea frags -> block out-stage [128][16] ----
    float* outS = (float*)(smem + SM_STAGE_B);
    {
        float* ob = outS + w * 32 * 16;
        #pragma unroll
        for (int m = 0; m < 2; m++)
            #pragma unroll
            for (int nt = 0; nt < 2; nt++) {
                *(float2*)(ob + (m * 16 + g) * 16 + nt * 8 + 2 * cq) =
                    make_float2(fc[m][nt][0], fc[m][nt][1]);
                *(float2*)(ob + (m * 16 + g + 8) * 16 + nt * 8 + 2 * cq) =
                    make_float2(fc[m][nt][2], fc[m][nt][3]);
            }
    }
    __syncthreads();

    // ---- sigma + analytic grad fold (acc reloaded from smem spill) ----
    float fea0  = outS[tid * 16];
    float pre   = fea0 + DENSITY_BIAS;
    float sigma = expf(pre);
    float gcl   = (pre < CLAMP_MAX) ? sigma : EXP10F;

    u64 gx2 = 0, gy2 = 0, gz2 = 0;
    #pragma unroll
    for (int l = 0; l < 4; l++) {
        u64 dl = mul2(dacc2[l], pk2(RES[l]));
        u64 ax = u2_to_u64(*(uint2*)(accS + l * 6 + 0));
        u64 ay = u2_to_u64(*(uint2*)(accS + l * 6 + 2));
        u64 az = u2_to_u64(*(uint2*)(accS + l * 6 + 4));
        gx2 = fma2(dl, ax, gx2);
        gy2 = fma2(dl, ay, gy2);
        gz2 = fma2(dl, az, gz2);
    }
    float2 pxx = upk(gx2), pyy = upk(gy2), pzz = upk(gz2);
    float gx = (pxx.x + pxx.y) * gcl;
    float gy = (pyy.x + pyy.y) * gcl;
    float gz = (pzz.x + pzz.y) * gcl;

    float nrm = sqrtf(fmaf(gx, gx, fmaf(gy, gy, gz * gz)));
    float inv = 1.0f / nrm;

    if (active) out[pid] = sigma;

    const int npts = min(128, n - blockIdx.x * 128);

    // fea copy-out (stage is contiguous [128][16] f32)
    {
        float4* src = (float4*)outS;
        float4* dst = (float4*)(out + (size_t)n) + (size_t)blockIdx.x * 512;
        int lim = npts * 4;
        for (int i = tid; i < lim; i += 128) dst[i] = src[i];
    }
    __syncthreads();

    // normals + grad via STAGE_A staging
    float* nsf = (float*)(smem + SM_STAGE_A);
    nsf[tid * 6 + 0] = gx * inv;
    nsf[tid * 6 + 1] = gy * inv;
    nsf[tid * 6 + 2] = gz * inv;
    nsf[tid * 6 + 3] = gx;
    nsf[tid * 6 + 4] = gy;
    nsf[tid * 6 + 5] = gz;
    __syncthreads();
    {
        float* ndst = out + (size_t)n * 17 + (size_t)blockIdx.x * 384;
        float* gdst = out + (size_t)n * 20 + (size_t)blockIdx.x * 384;
        int lim = npts * 3;
        for (int i = tid; i < lim; i += 128) {
            int p = i / 3, c = i - p * 3;
            ndst[i] = nsf[p * 6 + c];
        }
        for (int i = tid; i < lim; i += 128) {
            int p = i / 3, c = i - p * 3;
            gdst[i] = nsf[p * 6 + 3 + c];
        }
    }
}

extern "C" void kernel_launch(void* const* d_in, const int* in_sizes, int n_in,
                              void* d_out, int out_size)
{
    const float* pts   = (const float*)d_in[0];
    const float* table = (const float*)d_in[1];
    const float* W1    = (const float*)d_in[2];
    const float* W2    = (const float*)d_in[3];
    float* out = (float*)d_out;
    int n = in_sizes[0] / 3;

    setup_kernel<<<(NREC + 255) / 256, 256>>>(table, W1, W2);
    nerf_fused_kernel<<<(n + 127) / 128, 128>>>(pts, out, n);
}

// round 16
// speedup vs baseline: 1.2810x; 1.2810x over previous
#include <cuda_runtime.h>
#include <cstdint>

// vanillaMLP fused. Round 16: SIMT champion (round 9/10, 123.1us) +
//  - accx/y/z spilled to smem ([24][128] conflict-free) -> regs ~79->~58
//  - __launch_bounds__(128,7): 24 -> 28 warps/SM
//  - ALL staging dropped (pts, fea, normals, grad direct; L1 has headroom)
//    -> barrier-free main body (warp-local gather stage + syncwarp only)
// Outputs: [sigma N | fea N*16 | normals N*3 | grad N*3]

#define T_SIZE  524288
#define T_MASK  (T_SIZE - 1)
#define PRIME_Y 2654435761u
#define PRIME_Z 805459861u
#define DENSITY_BIAS (-1.0f)
#define CLAMP_MAX 10.0f
#define EXP10F 22026.465794806718f

#define D0 18
#define D1 24
#define D2 32
#define D3 44
#define OFF0 0
#define OFF1 5832
#define OFF2 19656
#define OFF3 52424
#define NDENSE 137608
#define NREC (NDENSE * 4)

__device__ __align__(128) float4 g_rec[NREC + 8];

// weight staging (device) and destination (constant)
__device__   float4 gW1r4[64 * 2];    // W1 rows, first 8 cols
__device__   float4 gW2t4[64 * 4];    // W2 transposed
__constant__ float4 cW1r4[64 * 2];
__constant__ float4 cW2t4[64 * 4];

typedef unsigned long long u64;
typedef uint32_t u32;

__device__ __forceinline__ u64 pk(float a, float b) {
    u64 r; asm("mov.b64 %0, {%1,%2};" : "=l"(r) : "f"(a), "f"(b)); return r;
}
__device__ __forceinline__ u64 pk2(float a) { return pk(a, a); }
__device__ __forceinline__ float2 upk(u64 v) {
    float2 r; asm("mov.b64 {%0,%1}, %2;" : "=f"(r.x), "=f"(r.y) : "l"(v)); return r;
}
__device__ __forceinline__ u64 fma2(u64 a, u64 b, u64 c) {
    u64 d; asm("fma.rn.f32x2 %0, %1, %2, %3;" : "=l"(d) : "l"(a), "l"(b), "l"(c)); return d;
}
__device__ __forceinline__ u64 mul2(u64 a, u64 b) {
    u64 d; asm("mul.rn.f32x2 %0, %1, %2;" : "=l"(d) : "l"(a), "l"(b)); return d;
}
__device__ __forceinline__ u64 add2(u64 a, u64 b) {
    u64 d; asm("add.rn.f32x2 %0, %1, %2;" : "=l"(d) : "l"(a), "l"(b)); return d;
}
__device__ __forceinline__ u64 neg2(u64 a) { return a ^ 0x8000000080000000ULL; }

// ---- fused setup: corner-records straight from the hash table + weights ----
__global__ void __launch_bounds__(256)
setup_kernel(const float* __restrict__ table,
             const float* __restrict__ W1,
             const float* __restrict__ W2)
{
    int idx = blockIdx.x * 256 + threadIdx.x;
    if (idx < NREC) {
        int cell = idx >> 2, q = idx & 3;
        int l, local, D;
        if (cell < OFF1)      { l = 0; local = cell;        D = D0; }
        else if (cell < OFF2) { l = 1; local = cell - OFF1; D = D1; }
        else if (cell < OFF3) { l = 2; local = cell - OFF2; D = D2; }
        else                  { l = 3; local = cell - OFF3; D = D3; }
        int z = local % D;
        int t = local / D;
        int y = t % D;
        int x = t / D;
        int ox = q >> 1, oy = q & 1;
        unsigned hb = (unsigned)(x + ox) ^ ((unsigned)(y + oy) * PRIME_Y);
        unsigned h0 = hb ^ ((unsigned)z * PRIME_Z);
        unsigned h1 = hb ^ ((unsigned)(z + 1) * PRIME_Z);
        const float2* __restrict__ tbl = (const float2*)table + (size_t)l * T_SIZE;
        float2 a = __ldg(tbl + (h0 & T_MASK));
        float2 b = __ldg(tbl + (h1 & T_MASK));
        g_rec[idx] = make_float4(a.x, a.y, b.x, b.y);
    }
    if (blockIdx.x == 0) {
        int i = threadIdx.x;
        if (i < 128) {
            int j = i >> 1, h = i & 1;
            const float* s = W1 + j * 32 + h * 4;
            gW1r4[i] = make_float4(s[0], s[1], s[2], s[3]);
        }
        int j = i >> 2, h = i & 3;
        gW2t4[i] = make_float4(W2[(4 * h + 0) * 64 + j], W2[(4 * h + 1) * 64 + j],
                               W2[(4 * h + 2) * 64 + j], W2[(4 * h + 3) * 64 + j]);
    }
}

__global__ void __launch_bounds__(128, 7)
nerf_fused_kernel(const float* __restrict__ pts,
                  float* __restrict__ out,
                  int n)
{
    __shared__ float4 sstage[128 * 5];     // warp-local gather stage (10240B)
    __shared__ u32    saccs[24 * 128];     // acc spill [component][tid] (12288B)

    const int tid  = threadIdx.x;
    const int lane = tid & 31;
    const int qbase = lane & ~3;
    const int lq    = lane & 3;

    const int pid = blockIdx.x * 128 + tid;
    const bool active = (pid < n);
    const int rp = active ? pid : (n - 1);

    float x = (__ldg(pts + (size_t)rp * 3 + 0) + 1.0f) * 0.5f;
    float y = (__ldg(pts + (size_t)rp * 3 + 1) + 1.0f) * 0.5f;
    float z = (__ldg(pts + (size_t)rp * 3 + 2) + 1.0f) * 0.5f;

    const float RES[4]  = {16.0f, 22.0f, 30.0f, 42.0f};
    const int   DIMS[4] = {D0, D1, D2, D3};
    const int   OFFS[4] = {OFF0, OFF1, OFF2, OFF3};

    u64 feat2[4];

    #pragma unroll
    for (int l = 0; l < 4; l++) {
        const float res = RES[l];
        const int   D   = DIMS[l];
        float fx = x * res, fy = y * res, fz = z * res;
        float x0 = floorf(fx), y0 = floorf(fy), z0 = floorf(fz);
        float frx = fx - x0, fry = fy - y0, frz = fz - z0;
        float mfx = 1.0f - frx, mfy = 1.0f - fry, mfz = 1.0f - frz;
        int rec = OFFS[l] + (((int)x0 * D + (int)y0) * D + (int)z0);

        // cooperative quad load into the warp-local stage slice
        #pragma unroll
        for (int i = 0; i < 4; i++) {
            int r = __shfl_sync(0xffffffffu, rec, qbase + i);
            float4 v = __ldg(g_rec + (size_t)r * 4 + lq);
            sstage[((tid & ~31) + qbase + i) * 5 + lq] = v;
        }
        __syncwarp();
        float4 v00 = sstage[tid * 5 + 0];
        float4 v01 = sstage[tid * 5 + 1];
        float4 v10 = sstage[tid * 5 + 2];
        float4 v11 = sstage[tid * 5 + 3];
        __syncwarp();   // reads complete before next level's stores

        u64 fz0 = pk2(mfz), fz1 = pk2(frz);
        u64 f01 = 0, ax = 0, ay = 0, az = 0;
        {   // (0,0)
            u64 t0 = pk(v00.x, v00.y), t1 = pk(v00.z, v00.w);
            u64 s = fma2(t0, fz0, mul2(t1, fz1));
            u64 d = add2(t1, neg2(t0));
            float wxy = mfx * mfy;
            f01 = fma2(pk2(wxy), s, f01);
            ax  = fma2(pk2(-mfy), s, ax);
            ay  = fma2(pk2(-mfx), s, ay);
            az  = fma2(pk2(wxy), d, az);
        }
        {   // (0,1)
            u64 t0 = pk(v01.x, v01.y), t1 = pk(v01.z, v01.w);
            u64 s = fma2(t0, fz0, mul2(t1, fz1));
            u64 d = add2(t1, neg2(t0));
            float wxy = mfx * fry;
            f01 = fma2(pk2(wxy), s, f01);
            ax  = fma2(pk2(-fry), s, ax);
            ay  = fma2(pk2( mfx), s, ay);
            az  = fma2(pk2(wxy), d, az);
        }
        {   // (1,0)
            u64 t0 = pk(v10.x, v10.y), t1 = pk(v10.z, v10.w);
            u64 s = fma2(t0, fz0, mul2(t1, fz1));
            u64 d = add2(t1, neg2(t0));
            float wxy = frx * mfy;
            f01 = fma2(pk2(wxy), s, f01);
            ax  = fma2(pk2( mfy), s, ax);
            ay  = fma2(pk2(-frx), s, ay);
            az  = fma2(pk2(wxy), d, az);
        }
        {   // (1,1)
            u64 t0 = pk(v11.x, v11.y), t1 = pk(v11.z, v11.w);
            u64 s = fma2(t0, fz0, mul2(t1, fz1));
            u64 d = add2(t1, neg2(t0));
            float wxy = frx * fry;
            f01 = fma2(pk2(wxy), s, f01);
            ax  = fma2(pk2( fry), s, ax);
            ay  = fma2(pk2( frx), s, ay);
            az  = fma2(pk2(wxy), d, az);
        }
        feat2[l] = f01;
        // spill encode partials (dead across the MLP) to conflict-free smem
        saccs[(l * 6 + 0) * 128 + tid] = (u32)ax;
        saccs[(l * 6 + 1) * 128 + tid] = (u32)(ax >> 32);
        saccs[(l * 6 + 2) * 128 + tid] = (u32)ay;
        saccs[(l * 6 + 3) * 128 + tid] = (u32)(ay >> 32);
        saccs[(l * 6 + 4) * 128 + tid] = (u32)az;
        saccs[(l * 6 + 5) * 128 + tid] = (u32)(az >> 32);
    }

    // ---- fused MLP forward + backward-prep (f32x2), weights from constant ----
    u64 fea2[8];
    u64 dacc2[4];
    #pragma unroll
    for (int i = 0; i < 8; i++) fea2[i] = 0;
    #pragma unroll
    for (int l = 0; l < 4; l++) dacc2[l] = 0;

    #pragma unroll 4
    for (int j = 0; j < 64; j++) {
        float4 wa = cW1r4[j * 2 + 0];
        float4 wb = cW1r4[j * 2 + 1];
        u64 a0 = pk(wa.x, wa.y), a1 = pk(wa.z, wa.w);
        u64 a2 = pk(wb.x, wb.y), a3 = pk(wb.z, wb.w);

        u64 s = fma2(feat2[0], a0,
                fma2(feat2[1], a1,
                fma2(feat2[2], a2,
                mul2(feat2[3], a3))));
        float2 sp = upk(s);
        float hj = sp.x + sp.y;
        float hp = fmaxf(hj, 0.0f);
        u64 hp2 = pk2(hp);

        float4 c0 = cW2t4[j * 4 + 0];
        float4 c1 = cW2t4[j * 4 + 1];
        float4 c2 = cW2t4[j * 4 + 2];
        float4 c3 = cW2t4[j * 4 + 3];
        fea2[0] = fma2(hp2, pk(c0.x, c0.y), fea2[0]);
        fea2[1] = fma2(hp2, pk(c0.z, c0.w), fea2[1]);
        fea2[2] = fma2(hp2, pk(c1.x, c1.y), fea2[2]);
        fea2[3] = fma2(hp2, pk(c1.z, c1.w), fea2[3]);
        fea2[4] = fma2(hp2, pk(c2.x, c2.y), fea2[4]);
        fea2[5] = fma2(hp2, pk(c2.z, c2.w), fea2[5]);
        fea2[6] = fma2(hp2, pk(c3.x, c3.y), fea2[6]);
        fea2[7] = fma2(hp2, pk(c3.z, c3.w), fea2[7]);

        float cm = (hj > 0.0f) ? c0.x : 0.0f;   // W2[0][j] gated by relu mask
        u64 cm2 = pk2(cm);
        dacc2[0] = fma2(cm2, a0, dacc2[0]);
        dacc2[1] = fma2(cm2, a1, dacc2[1]);
        dacc2[2] = fma2(cm2, a2, dacc2[2]);
        dacc2[3] = fma2(cm2, a3, dacc2[3]);
    }

    float2 fea01 = upk(fea2[0]);
    float pre   = fea01.x + DENSITY_BIAS;
    float sigma = expf(pre);
    float g     = (pre < CLAMP_MAX) ? sigma : EXP10F;

    // ---- packed gradient fold, acc reloaded from smem ----
    u64 gx2 = 0, gy2 = 0, gz2 = 0;
    #pragma unroll
    for (int l = 0; l < 4; l++) {
        u64 dl = mul2(dacc2[l], pk2(RES[l]));
        u64 ax = ((u64)saccs[(l * 6 + 1) * 128 + tid] << 32) | saccs[(l * 6 + 0) * 128 + tid];
        u64 ay = ((u64)saccs[(l * 6 + 3) * 128 + tid] << 32) | saccs[(l * 6 + 2) * 128 + tid];
        u64 az = ((u64)saccs[(l * 6 + 5) * 128 + tid] << 32) | saccs[(l * 6 + 4) * 128 + tid];
        gx2 = fma2(dl, ax, gx2);
        gy2 = fma2(dl, ay, gy2);
        gz2 = fma2(dl, az, gz2);
    }
    float2 pxx = upk(gx2), pyy = upk(gy2), pzz = upk(gz2);
    float gx = (pxx.x + pxx.y) * g;
    float gy = (pyy.x + pyy.y) * g;
    float gz = (pzz.x + pzz.y) * g;

    float nrm = sqrtf(fmaf(gx, gx, fmaf(gy, gy, gz * gz)));
    float inv = 1.0f / nrm;

    // ---- direct outputs ----
    if (active) {
        out[pid] = sigma;
        {
            float2 f0 = upk(fea2[0]), f1 = upk(fea2[1]);
            float2 f2 = upk(fea2[2]), f3 = upk(fea2[3]);
            float2 f4 = upk(fea2[4]), f5 = upk(fea2[5]);
            float2 f6 = upk(fea2[6]), f7 = upk(fea2[7]);
            float4* feaOut = (float4*)(out + (size_t)n) + (size_t)pid * 4;
            feaOut[0] = make_float4(f0.x, f0.y, f1.x, f1.y);
            feaOut[1] = make_float4(f2.x, f2.y, f3.x, f3.y);
            feaOut[2] = make_float4(f4.x, f4.y, f5.x, f5.y);
            feaOut[3] = make_float4(f6.x, f6.y, f7.x, f7.y);
        }
        float* nOut = out + (size_t)n * 17 + (size_t)pid * 3;
        nOut[0] = gx * inv; nOut[1] = gy * inv; nOut[2] = gz * inv;
        float* gOut = out + (size_t)n * 20 + (size_t)pid * 3;
        gOut[0] = gx; gOut[1] = gy; gOut[2] = gz;
    }
}

extern "C" void kernel_launch(void* const* d_in, const int* in_sizes, int n_in,
                              void* d_out, int out_size)
{
    const float* pts   = (const float*)d_in[0];
    const float* table = (const float*)d_in[1];
    const float* W1    = (const float*)d_in[2];
    const float* W2    = (const float*)d_in[3];
    float* out = (float*)d_out;
    int n = in_sizes[0] / 3;

    setup_kernel<<<(NREC + 255) / 256, 256>>>(table, W1, W2);

    void *c1 = nullptr, *c2 = nullptr, *g1 = nullptr, *g2 = nullptr;
    cudaGetSymbolAddress(&c1, cW1r4);
    cudaGetSymbolAddress(&c2, cW2t4);
    cudaGetSymbolAddress(&g1, gW1r4);
    cudaGetSymbolAddress(&g2, gW2t4);
    cudaMemcpyAsync(c1, g1, 64 * 2 * sizeof(float4), cudaMemcpyDeviceToDevice, 0);
    cudaMemcpyAsync(c2, g2, 64 * 4 * sizeof(float4), cudaMemcpyDeviceToDevice, 0);

    nerf_fused_kernel<<<(n + 127) / 128, 128>>>(pts, out, n);
}